// round 1
// baseline (speedup 1.0000x reference)
#include <cuda_runtime.h>
#include <cuda_bf16.h>
#include <cstdint>

#define BDIM 4096
#define KMOD 4
#define DIN  1024
#define HDIM 1024
#define CTXD 256
#define RHD  64
#define KDIM 4096  /* KMOD*DIN : concatenated reduction dim */

// ---------------- scratch (device globals: no runtime allocation) ----------------
__device__ float          g_c [BDIM * KMOD];                       // gate coeff c[b,k]
__device__ __nv_bfloat16  g_Ah[(size_t)BDIM * KDIM];               // hi(c*x)
__device__ __nv_bfloat16  g_Al[(size_t)BDIM * KDIM];               // lo(c*x)
__device__ __nv_bfloat16  g_Wh[(size_t)KDIM * HDIM];               // hi(W_enc)
__device__ __nv_bfloat16  g_Wl[(size_t)KDIM * HDIM];               // lo(W_enc)

// ---------------- router: Linear->LN->ReLU->Linear->ReLU->Linear->gate ----------------
__global__ void router_kernel(const float* __restrict__ context,
                              const float* __restrict__ gumbel,
                              const float* __restrict__ W1, const float* __restrict__ b1,
                              const float* __restrict__ gln, const float* __restrict__ bln,
                              const float* __restrict__ W2, const float* __restrict__ b2,
                              const float* __restrict__ W3, const float* __restrict__ b3,
                              const float* __restrict__ prior,
                              const float* __restrict__ fusion_w)
{
    __shared__ float ctx_s[8][CTXD];
    __shared__ float h1_s[8][RHD];
    __shared__ float h2_s[8][RHD / 2];
    const int warp = threadIdx.x >> 5, lane = threadIdx.x & 31;
    const int b = blockIdx.x * 8 + warp;

    const float* crow = context + (size_t)b * CTXD;
    for (int i = lane; i < CTXD; i += 32) ctx_s[warp][i] = crow[i];
    __syncwarp();

    float h[2];
#pragma unroll
    for (int jj = 0; jj < 2; jj++) {
        const int j = lane + jj * 32;
        float acc = b1[j];
        for (int i = 0; i < CTXD; i++) acc = fmaf(ctx_s[warp][i], W1[i * RHD + j], acc);
        h[jj] = acc;
    }
    float s  = h[0] + h[1];
    float sq = h[0] * h[0] + h[1] * h[1];
#pragma unroll
    for (int o = 16; o; o >>= 1) {
        s  += __shfl_xor_sync(0xffffffffu, s,  o);
        sq += __shfl_xor_sync(0xffffffffu, sq, o);
    }
    const float mu   = s * (1.0f / RHD);
    const float var  = sq * (1.0f / RHD) - mu * mu;
    const float rstd = rsqrtf(var + 1e-5f);
#pragma unroll
    for (int jj = 0; jj < 2; jj++) {
        const int j = lane + jj * 32;
        const float v = (h[jj] - mu) * rstd * gln[j] + bln[j];
        h1_s[warp][j] = fmaxf(v, 0.0f);
    }
    __syncwarp();
    float acc2 = b2[lane];
    for (int i = 0; i < RHD; i++) acc2 = fmaf(h1_s[warp][i], W2[i * (RHD / 2) + lane], acc2);
    h2_s[warp][lane] = fmaxf(acc2, 0.0f);
    __syncwarp();

    float logit = 0.0f;
    if (lane < KMOD) {
        logit = b3[lane] + prior[lane];
        for (int i = 0; i < RHD / 2; i++) logit = fmaf(h2_s[warp][i], W3[i * KMOD + lane], logit);
    }
    float lg[4];
#pragma unroll
    for (int k = 0; k < 4; k++) lg[k] = __shfl_sync(0xffffffffu, logit, k);

    if (lane == 0) {
        // softmax(fusion_w)
        float fw[4], m = -1e30f;
#pragma unroll
        for (int k = 0; k < 4; k++) { fw[k] = fusion_w[k]; m = fmaxf(m, fw[k]); }
        float se = 0.0f;
#pragma unroll
        for (int k = 0; k < 4; k++) { fw[k] = expf(fw[k] - m); se += fw[k]; }
        const float inv = 1.0f / se;
        // top-2 of probs == top-2 of logits (sigmoid monotonic); ties -> lower index
        int i1 = 0;
#pragma unroll
        for (int k = 1; k < 4; k++) if (lg[k] > lg[i1]) i1 = k;
        int i2 = (i1 == 0) ? 1 : 0;
#pragma unroll
        for (int k = 0; k < 4; k++) if (k != i1 && lg[k] > lg[i2]) i2 = k;
#pragma unroll
        for (int k = 0; k < 4; k++) {
            const float soft = 1.0f / (1.0f + expf(-(lg[k] + gumbel[b * KMOD + k])));
            const float mask = (k == i1 || k == i2) ? fmaxf(soft, 1.0f) : soft;
            const float cc   = (mask > 0.5f) ? (fw[k] * inv) * mask : 0.0f;
            g_c[b * KMOD + k] = cc;
        }
    }
}

// ---------------- hi/lo split of W_enc (elementwise; layout [k*DIN+d][h] already) ----------------
__global__ void split_w_kernel(const float* __restrict__ W)
{
    const size_t t = (size_t)blockIdx.x * blockDim.x + threadIdx.x;   // over KDIM*HDIM/4
    const float4 v = reinterpret_cast<const float4*>(W)[t];
    __nv_bfloat16 h0 = __float2bfloat16(v.x), h1 = __float2bfloat16(v.y);
    __nv_bfloat16 h2 = __float2bfloat16(v.z), h3 = __float2bfloat16(v.w);
    __nv_bfloat16 l0 = __float2bfloat16(v.x - __bfloat162float(h0));
    __nv_bfloat16 l1 = __float2bfloat16(v.y - __bfloat162float(h1));
    __nv_bfloat16 l2 = __float2bfloat16(v.z - __bfloat162float(h2));
    __nv_bfloat16 l3 = __float2bfloat16(v.w - __bfloat162float(h3));
    __nv_bfloat162 hp0 = __nv_bfloat162(h0, h1), hp1 = __nv_bfloat162(h2, h3);
    __nv_bfloat162 lp0 = __nv_bfloat162(l0, l1), lp1 = __nv_bfloat162(l2, l3);
    uint2 hv, lv;
    hv.x = *reinterpret_cast<uint32_t*>(&hp0); hv.y = *reinterpret_cast<uint32_t*>(&hp1);
    lv.x = *reinterpret_cast<uint32_t*>(&lp0); lv.y = *reinterpret_cast<uint32_t*>(&lp1);
    reinterpret_cast<uint2*>(g_Wh)[t] = hv;
    reinterpret_cast<uint2*>(g_Wl)[t] = lv;
}

// ---------------- gated hi/lo split of x: A[b, k*DIN+d] = c[b,k]*x[k,b,d] ----------------
__global__ void split_a_kernel(const float* __restrict__ x)
{
    const int t = blockIdx.x * blockDim.x + threadIdx.x;   // over KMOD*BDIM*DIN/4 (=4M)
    const int d4  = t & (DIN / 4 - 1);
    const int rem = t >> 8;                                 // DIN/4 == 256
    const int b   = rem & (BDIM - 1);
    const int mod = rem >> 12;                              // BDIM == 4096
    const float cc = g_c[b * KMOD + mod];
    float4 v = reinterpret_cast<const float4*>(x)[t];
    v.x *= cc; v.y *= cc; v.z *= cc; v.w *= cc;
    __nv_bfloat16 h0 = __float2bfloat16(v.x), h1 = __float2bfloat16(v.y);
    __nv_bfloat16 h2 = __float2bfloat16(v.z), h3 = __float2bfloat16(v.w);
    __nv_bfloat16 l0 = __float2bfloat16(v.x - __bfloat162float(h0));
    __nv_bfloat16 l1 = __float2bfloat16(v.y - __bfloat162float(h1));
    __nv_bfloat16 l2 = __float2bfloat16(v.z - __bfloat162float(h2));
    __nv_bfloat16 l3 = __float2bfloat16(v.w - __bfloat162float(h3));
    __nv_bfloat162 hp0 = __nv_bfloat162(h0, h1), hp1 = __nv_bfloat162(h2, h3);
    __nv_bfloat162 lp0 = __nv_bfloat162(l0, l1), lp1 = __nv_bfloat162(l2, l3);
    uint2 hv, lv;
    hv.x = *reinterpret_cast<uint32_t*>(&hp0); hv.y = *reinterpret_cast<uint32_t*>(&hp1);
    lv.x = *reinterpret_cast<uint32_t*>(&lp0); lv.y = *reinterpret_cast<uint32_t*>(&lp1);
    const size_t aidx4 = ((size_t)b * KDIM + (size_t)mod * DIN) / 4 + d4;
    reinterpret_cast<uint2*>(g_Ah)[aidx4] = hv;
    reinterpret_cast<uint2*>(g_Al)[aidx4] = lv;
}

// ---------------- main GEMM: out = Ah*Wh + Ah*Wl + Al*Wh + bias ----------------
#define BM 64
#define BN 128
#define BK 32
#define ASTR 40                       /* bf16 units; 80B row stride -> conflict-free ldmatrix */
#define BSTR 136                      /* bf16 units; 272B row stride */
#define A_BYTES (BM * ASTR * 2)       /* 5120  */
#define B_BYTES (BK * BSTR * 2)       /* 8704  */
#define STAGE_BYTES (2 * A_BYTES + 2 * B_BYTES)  /* 27648 */

__device__ __forceinline__ void cp16(uint32_t dst, const void* src)
{
    asm volatile("cp.async.cg.shared.global [%0], [%1], 16;\n" :: "r"(dst), "l"(src));
}
__device__ __forceinline__ void ldsm4(uint32_t* r, uint32_t addr)
{
    asm volatile("ldmatrix.sync.aligned.m8n8.x4.shared.b16 {%0,%1,%2,%3}, [%4];\n"
                 : "=r"(r[0]), "=r"(r[1]), "=r"(r[2]), "=r"(r[3]) : "r"(addr));
}
__device__ __forceinline__ void ldsm4t(uint32_t* r, uint32_t addr)
{
    asm volatile("ldmatrix.sync.aligned.m8n8.x4.trans.shared.b16 {%0,%1,%2,%3}, [%4];\n"
                 : "=r"(r[0]), "=r"(r[1]), "=r"(r[2]), "=r"(r[3]) : "r"(addr));
}
__device__ __forceinline__ void mma16816(float* d, const uint32_t* a, const uint32_t* b)
{
    asm volatile("mma.sync.aligned.m16n8k16.row.col.f32.bf16.bf16.f32 "
                 "{%0,%1,%2,%3},{%4,%5,%6,%7},{%8,%9},{%0,%1,%2,%3};\n"
                 : "+f"(d[0]), "+f"(d[1]), "+f"(d[2]), "+f"(d[3])
                 : "r"(a[0]), "r"(a[1]), "r"(a[2]), "r"(a[3]), "r"(b[0]), "r"(b[1]));
}

__global__ void __launch_bounds__(256, 2)
gemm_kernel(float* __restrict__ out, const float* __restrict__ b_enc)
{
    extern __shared__ char smem[];
    const int tid = threadIdx.x;
    const int warp = tid >> 5, lane = tid & 31;
    const int n0 = blockIdx.x * BN;
    const int m0 = blockIdx.y * BM;
    const int wm = warp & 1, wn = warp >> 1;   // warps: 2 (M) x 4 (N), warp tile 32x32

    const uint32_t sbase = (uint32_t)__cvta_generic_to_shared(smem);

    float d[2][4][4];
#pragma unroll
    for (int mt = 0; mt < 2; mt++)
#pragma unroll
        for (int nt = 0; nt < 4; nt++)
#pragma unroll
            for (int i = 0; i < 4; i++) d[mt][nt][i] = 0.0f;

    auto loadStage = [&](int s, int kt) {
        const uint32_t st = sbase + (uint32_t)s * STAGE_BYTES;
        const int bk = kt * BK;
#pragma unroll
        for (int i = 0; i < 2; i++) {                 // A: 512 x 16B chunks
            const int ca = tid + i * 256;
            const int var = ca >> 8, r = (ca >> 2) & 63, c = ca & 3;
            const __nv_bfloat16* src = (var ? g_Al : g_Ah) + (size_t)(m0 + r) * KDIM + bk + c * 8;
            cp16(st + var * A_BYTES + (uint32_t)(r * ASTR + c * 8) * 2, src);
        }
#pragma unroll
        for (int i = 0; i < 4; i++) {                 // B: 1024 x 16B chunks
            const int cb = tid + i * 256;
            const int var = cb >> 9, r = (cb >> 4) & 31, c = cb & 15;
            const __nv_bfloat16* src = (var ? g_Wl : g_Wh) + (size_t)(bk + r) * HDIM + n0 + c * 8;
            cp16(st + 2 * A_BYTES + var * B_BYTES + (uint32_t)(r * BSTR + c * 8) * 2, src);
        }
        asm volatile("cp.async.commit_group;\n");
    };

    loadStage(0, 0);
    const int KT = KDIM / BK;   // 128
    for (int kt = 0; kt < KT; kt++) {
        if (kt + 1 < KT) {
            loadStage((kt + 1) & 1, kt + 1);
            asm volatile("cp.async.wait_group 1;\n");
        } else {
            asm volatile("cp.async.wait_group 0;\n");
        }
        __syncthreads();
        const uint32_t st = sbase + (uint32_t)(kt & 1) * STAGE_BYTES;
#pragma unroll
        for (int ks = 0; ks < 2; ks++) {
            uint32_t ah[2][4], al[2][4];
#pragma unroll
            for (int mt = 0; mt < 2; mt++) {
                const int r = wm * 32 + mt * 16 + (lane & 15);
                const int cidx = ks * 16 + (lane >> 4) * 8;
                const uint32_t ao = (uint32_t)(r * ASTR + cidx) * 2;
                ldsm4(ah[mt], st + ao);
                ldsm4(al[mt], st + A_BYTES + ao);
            }
#pragma unroll
            for (int grp = 0; grp < 2; grp++) {
                uint32_t bh[4], bl[4];
                const int part = lane >> 3;
                const int kr = ks * 16 + (part & 1) * 8 + (lane & 7);
                const int ncol = wn * 32 + grp * 16 + (part >> 1) * 8;
                const uint32_t bo = st + 2 * A_BYTES + (uint32_t)(kr * BSTR + ncol) * 2;
                ldsm4t(bh, bo);
                ldsm4t(bl, bo + B_BYTES);
#pragma unroll
                for (int nt2 = 0; nt2 < 2; nt2++) {
                    const int nt = grp * 2 + nt2;
#pragma unroll
                    for (int mt = 0; mt < 2; mt++) {
                        mma16816(d[mt][nt], ah[mt], &bh[nt2 * 2]);   // hi*hi
                        mma16816(d[mt][nt], ah[mt], &bl[nt2 * 2]);   // hi*lo
                        mma16816(d[mt][nt], al[mt], &bh[nt2 * 2]);   // lo*hi
                    }
                }
            }
        }
        __syncthreads();
    }

    // epilogue: + sum_k c[b,k]*b_enc[k,h]
#pragma unroll
    for (int mt = 0; mt < 2; mt++) {
        const int rbase = m0 + wm * 32 + mt * 16 + (lane >> 2);
#pragma unroll
        for (int half = 0; half < 2; half++) {
            const int r = rbase + half * 8;
            const float4 c4 = *reinterpret_cast<const float4*>(&g_c[r * KMOD]);
#pragma unroll
            for (int nt = 0; nt < 4; nt++) {
                const int c = n0 + wn * 32 + nt * 8 + (lane & 3) * 2;
                const float bias0 = c4.x * b_enc[0 * HDIM + c]     + c4.y * b_enc[1 * HDIM + c]
                                  + c4.z * b_enc[2 * HDIM + c]     + c4.w * b_enc[3 * HDIM + c];
                const float bias1 = c4.x * b_enc[0 * HDIM + c + 1] + c4.y * b_enc[1 * HDIM + c + 1]
                                  + c4.z * b_enc[2 * HDIM + c + 1] + c4.w * b_enc[3 * HDIM + c + 1];
                out[(size_t)r * HDIM + c]     = d[mt][nt][half * 2 + 0] + bias0;
                out[(size_t)r * HDIM + c + 1] = d[mt][nt][half * 2 + 1] + bias1;
            }
        }
    }
}

// ---------------- launch ----------------
extern "C" void kernel_launch(void* const* d_in, const int* in_sizes, int n_in,
                              void* d_out, int out_size)
{
    const float* context  = (const float*)d_in[0];
    const float* x        = (const float*)d_in[1];
    const float* gumbel   = (const float*)d_in[2];
    const float* W1       = (const float*)d_in[3];
    const float* b1       = (const float*)d_in[4];
    const float* gln      = (const float*)d_in[5];
    const float* bln      = (const float*)d_in[6];
    const float* W2       = (const float*)d_in[7];
    const float* b2       = (const float*)d_in[8];
    const float* W3       = (const float*)d_in[9];
    const float* b3       = (const float*)d_in[10];
    const float* prior    = (const float*)d_in[11];
    const float* W_enc    = (const float*)d_in[12];
    const float* b_enc    = (const float*)d_in[13];
    const float* fusion_w = (const float*)d_in[14];
    float* out = (float*)d_out;

    router_kernel<<<BDIM / 8, 256>>>(context, gumbel, W1, b1, gln, bln, W2, b2, W3, b3,
                                     prior, fusion_w);
    split_a_kernel<<<(KMOD * BDIM * (DIN / 4)) / 256, 256>>>(x);
    split_w_kernel<<<(KDIM * (HDIM / 4)) / 256, 256>>>(W_enc);

    cudaFuncSetAttribute(gemm_kernel, cudaFuncAttributeMaxDynamicSharedMemorySize,
                         STAGE_BYTES * 2);
    gemm_kernel<<<dim3(HDIM / BN, BDIM / BM), 256, STAGE_BYTES * 2>>>(out, b_enc);
}